// round 1
// baseline (speedup 1.0000x reference)
#include <cuda_runtime.h>
#include <math.h>

#define B_    16
#define C_    64
#define H_    128
#define W_    128
#define E_    8
#define OC_   64
#define NTOT  512          // E_*OC_
#define KTOT  576          // C_*9
#define KCHUNK 72          // 8 ic * 9 taps
#define NCHUNKS 8
#define TILE_W 16
#define TILE_H 8

// scratch (no cudaMalloc allowed)
__device__ float g_w2[KTOT * NTOT];          // [k][n], n = oc*8 + e
__device__ float g_gate[B_ * 16 * 16 * E_];  // softmax gates per patch
__device__ float g_S[E_ * 32];               // summed pos-weight per (e, feat)
__device__ float g_FS[16 * 16 * E_];         // fourier+bias logit part per (ph,pw,e)

// ---------------- weight reshape: expert_w[e,oc,ic,ky,kx] -> g_w2[ic*9+tap][oc*8+e]
__global__ void prep_w(const float* __restrict__ ew) {
    int i = blockIdx.x * 256 + threadIdx.x;
    if (i >= KTOT * NTOT) return;
    int k = i >> 9, n = i & 511;
    int ic = k / 9, tap = k % 9;
    int oc = n >> 3, e = n & 7;
    g_w2[i] = ew[(((e * OC_ + oc) * C_ + ic) * 9) + tap];
}

// ---------------- fourier/bias part of the gate logits (constant per patch pos)
__global__ void prep_fs(const float* __restrict__ gw, const float* __restrict__ gb) {
    int t = threadIdx.x; // 256
    // S[e][j] = sum over the 64 patch pixels of gate_w[e, (64+j)*64 + pix]
    {
        int e = t >> 5, j = t & 31;
        float s = 0.f;
        const float* p = gw + e * 6144 + (64 + j) * 64;
        #pragma unroll 8
        for (int q = 0; q < 64; q++) s += p[q];
        g_S[e * 32 + j] = s;
    }
    __syncthreads();
    const float PI = 3.14159265358979323846f;
    for (int i = t; i < 16 * 16 * E_; i += 256) {
        int e = i & 7, pw = (i >> 3) & 15, ph = i >> 7;
        float acc = gb[e];
        const float* S = g_S + e * 32;
        float cy = (ph + 0.5f) / 16.0f, cx = (pw + 0.5f) / 16.0f;
        #pragma unroll
        for (int f = 0; f < 8; f++) {
            float freq = (float)(1 << f) * PI;
            float sy, cyv, sx, cxv;
            sincosf(cy * freq, &sy, &cyv);
            sincosf(cx * freq, &sx, &cxv);
            acc += sy * S[f] + cyv * S[8 + f] + sx * S[16 + f] + cxv * S[24 + f];
        }
        g_FS[i] = acc;
    }
}

// ---------------- per-patch gate softmax. one block per (b, ph, pw), 64 threads
__global__ void gate_k(const float* __restrict__ x, const float* __restrict__ gw) {
    int bid = blockIdx.x;
    int pw = bid & 15, ph = (bid >> 4) & 15, b = bid >> 8;
    int t = threadIdx.x;            // 0..63 -> pixel (py,px)
    int py = t >> 3, px = t & 7;
    int h = ph * 8 + py, w = pw * 8 + px;
    const float* xp = x + ((b * C_) * H_ + h) * W_ + w;

    float part[E_];
    #pragma unroll
    for (int e = 0; e < E_; e++) part[e] = 0.f;

    for (int c = 0; c < C_; c++) {
        float xv = xp[c * H_ * W_];
        const float* g = gw + c * 64 + t;
        #pragma unroll
        for (int e = 0; e < E_; e++) part[e] += xv * g[e * 6144];
    }
    // reduce over 64 pixels (2 warps)
    #pragma unroll
    for (int off = 16; off; off >>= 1) {
        #pragma unroll
        for (int e = 0; e < E_; e++)
            part[e] += __shfl_xor_sync(0xffffffffu, part[e], off);
    }
    __shared__ float red[2][E_];
    if ((t & 31) == 0) {
        #pragma unroll
        for (int e = 0; e < E_; e++) red[t >> 5][e] = part[e];
    }
    __syncthreads();
    __shared__ float logits[E_];
    if (t < E_) logits[t] = red[0][t] + red[1][t] + g_FS[(ph * 16 + pw) * 8 + t];
    __syncthreads();
    if (t == 0) {
        float mx = logits[0];
        #pragma unroll
        for (int e = 1; e < E_; e++) mx = fmaxf(mx, logits[e]);
        float ex[E_], se = 0.f;
        #pragma unroll
        for (int e = 0; e < E_; e++) { ex[e] = __expf(logits[e] - mx); se += ex[e]; }
        float inv = 1.f / se;
        float* gp = g_gate + ((b * 16 + ph) * 16 + pw) * 8;
        #pragma unroll
        for (int e = 0; e < E_; e++) gp[e] = ex[e] * inv;
    }
}

// ---------------- fused conv + relu + gated combine
// block: 128 pixels (16x8 tile) x 128 n (16 oc x 8 experts); 256 threads,
// thread: 8 pixels (one row) x 8 n (all experts of one oc).
__global__ void __launch_bounds__(256, 2)
moe_conv(const float* __restrict__ x, const float* __restrict__ eb,
         float* __restrict__ out) {
    int bid = blockIdx.x;
    int nb = bid & 3;
    int tx = (bid >> 2) & 7;
    int ty = (bid >> 5) & 15;
    int b  = bid >> 9;
    int x0 = tx * TILE_W, y0 = ty * TILE_H;
    int t = threadIdx.x;
    int n_thr = t & 15, m_thr = t >> 4;
    int r = m_thr >> 1, c0 = (m_thr & 1) * 8;

    __shared__ __align__(16) float Bs[KCHUNK][128];
    __shared__ __align__(16) float Xs[8][10][20];

    float acc[8][8];
    #pragma unroll
    for (int j = 0; j < 8; j++)
        #pragma unroll
        for (int e = 0; e < 8; e++) acc[j][e] = 0.f;

    for (int ch = 0; ch < NCHUNKS; ++ch) {
        int ic0 = ch * 8;
        int k0 = ic0 * 9;
        // load B tile (72 x 128 floats) via float4
        for (int i = t; i < KCHUNK * 32; i += 256) {
            int kl = i >> 5, q = i & 31;
            *(((float4*)&Bs[kl][0]) + q) =
                *(const float4*)(g_w2 + (k0 + kl) * NTOT + nb * 128 + q * 4);
        }
        // load X tile with halo: 8 ic x 10 rows x 18 cols (padded width 20)
        const float* xb = x + (b * C_ + ic0) * (H_ * W_);
        for (int i = t; i < 1440; i += 256) {
            int ic = i / 180, rem = i % 180;
            int yy = rem / 18, xx = rem % 18;
            int gy = y0 - 1 + yy, gx = x0 - 1 + xx;
            float v = 0.f;
            if ((unsigned)gy < 128u && (unsigned)gx < 128u)
                v = xb[ic * (H_ * W_) + gy * W_ + gx];
            Xs[ic][yy][xx] = v;
        }
        __syncthreads();

        #pragma unroll
        for (int ic = 0; ic < 8; ++ic) {
            #pragma unroll
            for (int dy = 0; dy < 3; ++dy) {
                float row[10];
                const float* rp = &Xs[ic][r + dy][c0];
                float4 t0 = *(const float4*)rp;
                float4 t1 = *(const float4*)(rp + 4);
                row[0] = t0.x; row[1] = t0.y; row[2] = t0.z; row[3] = t0.w;
                row[4] = t1.x; row[5] = t1.y; row[6] = t1.z; row[7] = t1.w;
                row[8] = rp[8]; row[9] = rp[9];
                #pragma unroll
                for (int dx = 0; dx < 3; ++dx) {
                    int kl = ic * 9 + dy * 3 + dx;
                    float4 b0 = *(const float4*)&Bs[kl][n_thr * 8];
                    float4 b1 = *(const float4*)&Bs[kl][n_thr * 8 + 4];
                    #pragma unroll
                    for (int j = 0; j < 8; j++) {
                        float a = row[dx + j];
                        acc[j][0] = fmaf(a, b0.x, acc[j][0]);
                        acc[j][1] = fmaf(a, b0.y, acc[j][1]);
                        acc[j][2] = fmaf(a, b0.z, acc[j][2]);
                        acc[j][3] = fmaf(a, b0.w, acc[j][3]);
                        acc[j][4] = fmaf(a, b1.x, acc[j][4]);
                        acc[j][5] = fmaf(a, b1.y, acc[j][5]);
                        acc[j][6] = fmaf(a, b1.z, acc[j][6]);
                        acc[j][7] = fmaf(a, b1.w, acc[j][7]);
                    }
                }
            }
        }
        __syncthreads();
    }

    // epilogue: bias + relu + gate-weighted sum over experts, write out[b,oc,h,w]
    int oc = nb * 16 + n_thr;
    float bias[8];
    #pragma unroll
    for (int e = 0; e < 8; e++) bias[e] = eb[e * OC_ + oc];

    int h = y0 + r, w0 = x0 + c0;
    int patch = (b * 16 + (h >> 3)) * 16 + (w0 >> 3);
    const float* gp = g_gate + patch * 8;
    float gv[8];
    #pragma unroll
    for (int e = 0; e < 8; e++) gv[e] = gp[e];

    float res[8];
    #pragma unroll
    for (int j = 0; j < 8; j++) {
        float s = 0.f;
        #pragma unroll
        for (int e = 0; e < 8; e++)
            s += gv[e] * fmaxf(acc[j][e] + bias[e], 0.f);
        res[j] = s;
    }
    float* op = out + ((b * OC_ + oc) * H_ + h) * W_ + w0;
    *(float4*)op       = make_float4(res[0], res[1], res[2], res[3]);
    *(float4*)(op + 4) = make_float4(res[4], res[5], res[6], res[7]);
}

extern "C" void kernel_launch(void* const* d_in, const int* in_sizes, int n_in,
                              void* d_out, int out_size) {
    const float* x  = (const float*)d_in[0];
    const float* ew = (const float*)d_in[1];
    const float* eb = (const float*)d_in[2];
    const float* gw = (const float*)d_in[3];
    const float* gb = (const float*)d_in[4];
    float* out = (float*)d_out;

    prep_w<<<(KTOT * NTOT + 255) / 256, 256>>>(ew);
    prep_fs<<<1, 256>>>(gw, gb);
    gate_k<<<B_ * 16 * 16, 64>>>(x, gw);
    moe_conv<<<B_ * 16 * 16 * 4 / 2, 256>>>(x, eb, out);  // 8192 blocks
}

// round 2
// speedup vs baseline: 1.1354x; 1.1354x over previous
#include <cuda_runtime.h>
#include <math.h>

#define B_    16
#define C_    64
#define H_    128
#define W_    128
#define E_    8
#define OC_   64
#define NTOT  512          // E_*OC_
#define KTOT  576          // C_*9
#define KCHUNK 72          // 8 ic * 9 taps
#define NCHUNKS 8
#define TILE_W 16
#define TILE_H 8

// stage = B tile (72x128) + X tile (8x10x20 padded)
#define STAGE_B_FLOATS (KCHUNK * 128)          // 9216
#define STAGE_X_FLOATS (8 * 10 * 20)           // 1600
#define STAGE_FLOATS   (STAGE_B_FLOATS + STAGE_X_FLOATS)   // 10816
#define DYN_SMEM_BYTES (2 * STAGE_FLOATS * 4)  // 86528

// scratch (no cudaMalloc allowed)
__device__ float g_w2[KTOT * NTOT];          // [k][n], n = oc*8 + e
__device__ float g_gate[B_ * 16 * 16 * E_];  // softmax gates per patch
__device__ float g_S[E_ * 32];               // summed pos-weight per (e, feat)
__device__ float g_FS[16 * 16 * E_];         // fourier+bias logit part per (ph,pw,e)

// ---------------- weight reshape: expert_w[e,oc,ic,ky,kx] -> g_w2[ic*9+tap][oc*8+e]
__global__ void prep_w(const float* __restrict__ ew) {
    int i = blockIdx.x * 256 + threadIdx.x;
    if (i >= KTOT * NTOT) return;
    int k = i >> 9, n = i & 511;
    int ic = k / 9, tap = k % 9;
    int oc = n >> 3, e = n & 7;
    g_w2[i] = ew[(((e * OC_ + oc) * C_ + ic) * 9) + tap];
}

// ---------------- fourier/bias part of the gate logits (constant per patch pos)
__global__ void prep_fs(const float* __restrict__ gw, const float* __restrict__ gb) {
    int t = threadIdx.x; // 256
    {
        int e = t >> 5, j = t & 31;
        float s = 0.f;
        const float* p = gw + e * 6144 + (64 + j) * 64;
        #pragma unroll 8
        for (int q = 0; q < 64; q++) s += p[q];
        g_S[e * 32 + j] = s;
    }
    __syncthreads();
    const float PI = 3.14159265358979323846f;
    for (int i = t; i < 16 * 16 * E_; i += 256) {
        int e = i & 7, pw = (i >> 3) & 15, ph = i >> 7;
        float acc = gb[e];
        const float* S = g_S + e * 32;
        float cy = (ph + 0.5f) / 16.0f, cx = (pw + 0.5f) / 16.0f;
        #pragma unroll
        for (int f = 0; f < 8; f++) {
            float freq = (float)(1 << f) * PI;
            float sy, cyv, sx, cxv;
            sincosf(cy * freq, &sy, &cyv);
            sincosf(cx * freq, &sx, &cxv);
            acc += sy * S[f] + cyv * S[8 + f] + sx * S[16 + f] + cxv * S[24 + f];
        }
        g_FS[i] = acc;
    }
}

// ---------------- per-patch gate softmax. one block per (b, ph, pw), 64 threads
__global__ void gate_k(const float* __restrict__ x, const float* __restrict__ gw) {
    int bid = blockIdx.x;
    int pw = bid & 15, ph = (bid >> 4) & 15, b = bid >> 8;
    int t = threadIdx.x;            // 0..63 -> pixel (py,px)
    int py = t >> 3, px = t & 7;
    int h = ph * 8 + py, w = pw * 8 + px;
    const float* xp = x + ((b * C_) * H_ + h) * W_ + w;

    float part[E_];
    #pragma unroll
    for (int e = 0; e < E_; e++) part[e] = 0.f;

    for (int c = 0; c < C_; c++) {
        float xv = xp[c * H_ * W_];
        const float* g = gw + c * 64 + t;
        #pragma unroll
        for (int e = 0; e < E_; e++) part[e] += xv * g[e * 6144];
    }
    #pragma unroll
    for (int off = 16; off; off >>= 1) {
        #pragma unroll
        for (int e = 0; e < E_; e++)
            part[e] += __shfl_xor_sync(0xffffffffu, part[e], off);
    }
    __shared__ float red[2][E_];
    if ((t & 31) == 0) {
        #pragma unroll
        for (int e = 0; e < E_; e++) red[t >> 5][e] = part[e];
    }
    __syncthreads();
    __shared__ float logits[E_];
    if (t < E_) logits[t] = red[0][t] + red[1][t] + g_FS[(ph * 16 + pw) * 8 + t];
    __syncthreads();
    if (t == 0) {
        float mx = logits[0];
        #pragma unroll
        for (int e = 1; e < E_; e++) mx = fmaxf(mx, logits[e]);
        float ex[E_], se = 0.f;
        #pragma unroll
        for (int e = 0; e < E_; e++) { ex[e] = __expf(logits[e] - mx); se += ex[e]; }
        float inv = 1.f / se;
        float* gp = g_gate + ((b * 16 + ph) * 16 + pw) * 8;
        #pragma unroll
        for (int e = 0; e < E_; e++) gp[e] = ex[e] * inv;
    }
}

// ---------------- cp.async helpers
__device__ __forceinline__ void cp16(unsigned dst, const void* src) {
    asm volatile("cp.async.cg.shared.global [%0], [%1], 16;\n" ::
                 "r"(dst), "l"(src));
}
__device__ __forceinline__ void cp4z(unsigned dst, const void* src, int srcsize) {
    asm volatile("cp.async.ca.shared.global [%0], [%1], 4, %2;\n" ::
                 "r"(dst), "l"(src), "r"(srcsize));
}
__device__ __forceinline__ void cp_commit() {
    asm volatile("cp.async.commit_group;\n" ::);
}
__device__ __forceinline__ void cp_wait0() {
    asm volatile("cp.async.wait_group 0;\n" ::);
}

// issue async loads of one k-chunk into a stage buffer
__device__ __forceinline__ void issue_loads(float* stage, const float* __restrict__ x,
                                            int b, int ch, int nb, int x0, int y0, int t) {
    unsigned sb = (unsigned)__cvta_generic_to_shared(stage);
    int k0 = ch * KCHUNK;
    // B tile: 72 rows x 128 floats = 2304 float4
    #pragma unroll
    for (int it = 0; it < 9; it++) {
        int i = t + it * 256;                 // 9*256 = 2304 exactly
        int kl = i >> 5, q = i & 31;
        const float* g = g_w2 + (k0 + kl) * NTOT + nb * 128 + q * 4;
        cp16(sb + (unsigned)((kl * 128 + q * 4) * 4), g);
    }
    // X tile: 8 ic x 10 rows x 18 cols (store pitch 20), zero-filled halo
    unsigned xs = sb + STAGE_B_FLOATS * 4;
    const float* xb = x + (b * C_ + ch * 8) * (H_ * W_);
    #pragma unroll
    for (int it = 0; it < 6; it++) {
        int i = t + it * 256;
        if (i < 1440) {
            int ic = i / 180, rem = i - ic * 180;
            int yy = rem / 18, xx = rem - yy * 18;
            int gy = y0 - 1 + yy, gx = x0 - 1 + xx;
            bool ok = ((unsigned)gy < 128u) && ((unsigned)gx < 128u);
            const float* g = ok ? (xb + ic * (H_ * W_) + gy * W_ + gx) : xb;
            cp4z(xs + (unsigned)((ic * 200 + yy * 20 + xx) * 4), g, ok ? 4 : 0);
        }
    }
}

// ---------------- fused conv + relu + gated combine (double-buffered cp.async)
__global__ void __launch_bounds__(256, 2)
moe_conv(const float* __restrict__ x, const float* __restrict__ eb,
         float* __restrict__ out) {
    extern __shared__ float dynsmem[];
    int bid = blockIdx.x;
    int nb = bid & 3;
    int tx = (bid >> 2) & 7;
    int ty = (bid >> 5) & 15;
    int b  = bid >> 9;
    int x0 = tx * TILE_W, y0 = ty * TILE_H;
    int t = threadIdx.x;
    int n_thr = t & 15, m_thr = t >> 4;
    int r = m_thr >> 1, c0 = (m_thr & 1) * 8;

    float acc[8][8];
    #pragma unroll
    for (int j = 0; j < 8; j++)
        #pragma unroll
        for (int e = 0; e < 8; e++) acc[j][e] = 0.f;

    issue_loads(dynsmem, x, b, 0, nb, x0, y0, t);
    cp_commit();

    for (int ch = 0; ch < NCHUNKS; ++ch) {
        cp_wait0();
        __syncthreads();
        if (ch + 1 < NCHUNKS) {
            issue_loads(dynsmem + ((ch + 1) & 1) * STAGE_FLOATS, x, b, ch + 1, nb, x0, y0, t);
            cp_commit();
        }
        float* stage = dynsmem + (ch & 1) * STAGE_FLOATS;
        float (*Bs)[128]    = (float(*)[128])stage;
        float (*Xs)[10][20] = (float(*)[10][20])(stage + STAGE_B_FLOATS);

        #pragma unroll
        for (int ic = 0; ic < 8; ++ic) {
            #pragma unroll
            for (int dy = 0; dy < 3; ++dy) {
                float row[10];
                const float* rp = &Xs[ic][r + dy][c0];
                float4 t0 = *(const float4*)rp;
                float4 t1 = *(const float4*)(rp + 4);
                row[0] = t0.x; row[1] = t0.y; row[2] = t0.z; row[3] = t0.w;
                row[4] = t1.x; row[5] = t1.y; row[6] = t1.z; row[7] = t1.w;
                row[8] = rp[8]; row[9] = rp[9];
                #pragma unroll
                for (int dx = 0; dx < 3; ++dx) {
                    int kl = ic * 9 + dy * 3 + dx;
                    float4 b0 = *(const float4*)&Bs[kl][n_thr * 8];
                    float4 b1 = *(const float4*)&Bs[kl][n_thr * 8 + 4];
                    #pragma unroll
                    for (int j = 0; j < 8; j++) {
                        float a = row[dx + j];
                        acc[j][0] = fmaf(a, b0.x, acc[j][0]);
                        acc[j][1] = fmaf(a, b0.y, acc[j][1]);
                        acc[j][2] = fmaf(a, b0.z, acc[j][2]);
                        acc[j][3] = fmaf(a, b0.w, acc[j][3]);
                        acc[j][4] = fmaf(a, b1.x, acc[j][4]);
                        acc[j][5] = fmaf(a, b1.y, acc[j][5]);
                        acc[j][6] = fmaf(a, b1.z, acc[j][6]);
                        acc[j][7] = fmaf(a, b1.w, acc[j][7]);
                    }
                }
            }
        }
        __syncthreads();
    }

    // epilogue: bias + relu + gate-weighted sum over experts, write out[b,oc,h,w]
    int oc = nb * 16 + n_thr;
    float bias[8];
    #pragma unroll
    for (int e = 0; e < 8; e++) bias[e] = eb[e * OC_ + oc];

    int h = y0 + r, w0 = x0 + c0;
    int patch = (b * 16 + (h >> 3)) * 16 + (w0 >> 3);
    const float* gp = g_gate + patch * 8;
    float gv[8];
    #pragma unroll
    for (int e = 0; e < 8; e++) gv[e] = gp[e];

    float res[8];
    #pragma unroll
    for (int j = 0; j < 8; j++) {
        float s = 0.f;
        #pragma unroll
        for (int e = 0; e < 8; e++)
            s += gv[e] * fmaxf(acc[j][e] + bias[e], 0.f);
        res[j] = s;
    }
    float* op = out + ((b * OC_ + oc) * H_ + h) * W_ + w0;
    *(float4*)op       = make_float4(res[0], res[1], res[2], res[3]);
    *(float4*)(op + 4) = make_float4(res[4], res[5], res[6], res[7]);
}

extern "C" void kernel_launch(void* const* d_in, const int* in_sizes, int n_in,
                              void* d_out, int out_size) {
    const float* x  = (const float*)d_in[0];
    const float* ew = (const float*)d_in[1];
    const float* eb = (const float*)d_in[2];
    const float* gw = (const float*)d_in[3];
    const float* gb = (const float*)d_in[4];
    float* out = (float*)d_out;

    static bool attr_done = false;
    if (!attr_done) {
        cudaFuncSetAttribute(moe_conv, cudaFuncAttributeMaxDynamicSharedMemorySize,
                             DYN_SMEM_BYTES);
        attr_done = true;
    }

    prep_w<<<(KTOT * NTOT + 255) / 256, 256>>>(ew);
    prep_fs<<<1, 256>>>(gw, gb);
    gate_k<<<B_ * 16 * 16, 64>>>(x, gw);
    moe_conv<<<B_ * 16 * 16 * 4 / 2, 256, DYN_SMEM_BYTES>>>(x, eb, out);
}

// round 3
// speedup vs baseline: 1.1377x; 1.0020x over previous
#include <cuda_runtime.h>
#include <math.h>

#define B_    16
#define C_    64
#define H_    128
#define W_    128
#define E_    8
#define OC_   64
#define NTOT  512          // E_*OC_
#define KTOT  576          // C_*9
#define KCHUNK 72          // 8 ic * 9 taps
#define NCHUNKS 8
#define TILE_W 16
#define TILE_H 8

// stage = B tile (72x128) + X tile (8x10x20 padded)
#define STAGE_B_FLOATS (KCHUNK * 128)          // 9216
#define STAGE_X_FLOATS (8 * 10 * 20)           // 1600
#define STAGE_FLOATS   (STAGE_B_FLOATS + STAGE_X_FLOATS)   // 10816
#define DYN_SMEM_BYTES (2 * STAGE_FLOATS * 4)  // 86528

// scratch (no cudaMalloc allowed)
__device__ float g_w2[KTOT * NTOT];          // [k][n], n = oc*8 + e
__device__ float g_gate[B_ * 16 * 16 * E_];  // softmax gates per patch
__device__ float g_S[E_ * 32];               // summed pos-weight per (e, feat)
__device__ float g_FS[16 * 16 * E_];         // fourier+bias logit part per (ph,pw,e)

// ---------------- weight reshape: expert_w[e,oc,ic,ky,kx] -> g_w2[ic*9+tap][oc*8+e]
__global__ void prep_w(const float* __restrict__ ew) {
    int i = blockIdx.x * 256 + threadIdx.x;
    if (i >= KTOT * NTOT) return;
    int k = i >> 9, n = i & 511;
    int ic = k / 9, tap = k % 9;
    int oc = n >> 3, e = n & 7;
    g_w2[i] = ew[(((e * OC_ + oc) * C_ + ic) * 9) + tap];
}

// ---------------- fourier/bias part of the gate logits (constant per patch pos)
__global__ void prep_fs(const float* __restrict__ gw, const float* __restrict__ gb) {
    int t = threadIdx.x; // 256
    {
        int e = t >> 5, j = t & 31;
        float s = 0.f;
        const float* p = gw + e * 6144 + (64 + j) * 64;
        #pragma unroll 8
        for (int q = 0; q < 64; q++) s += p[q];
        g_S[e * 32 + j] = s;
    }
    __syncthreads();
    const float PI = 3.14159265358979323846f;
    for (int i = t; i < 16 * 16 * E_; i += 256) {
        int e = i & 7, pw = (i >> 3) & 15, ph = i >> 7;
        float acc = gb[e];
        const float* S = g_S + e * 32;
        float cy = (ph + 0.5f) / 16.0f, cx = (pw + 0.5f) / 16.0f;
        #pragma unroll
        for (int f = 0; f < 8; f++) {
            float freq = (float)(1 << f) * PI;
            float sy, cyv, sx, cxv;
            sincosf(cy * freq, &sy, &cyv);
            sincosf(cx * freq, &sx, &cxv);
            acc += sy * S[f] + cyv * S[8 + f] + sx * S[16 + f] + cxv * S[24 + f];
        }
        g_FS[i] = acc;
    }
}

// ---------------- per-patch gate softmax. one block per (b, ph, pw), 64 threads
__global__ void gate_k(const float* __restrict__ x, const float* __restrict__ gw) {
    int bid = blockIdx.x;
    int pw = bid & 15, ph = (bid >> 4) & 15, b = bid >> 8;
    int t = threadIdx.x;            // 0..63 -> pixel (py,px)
    int py = t >> 3, px = t & 7;
    int h = ph * 8 + py, w = pw * 8 + px;
    const float* xp = x + ((b * C_) * H_ + h) * W_ + w;

    float part[E_];
    #pragma unroll
    for (int e = 0; e < E_; e++) part[e] = 0.f;

    for (int c = 0; c < C_; c++) {
        float xv = xp[c * H_ * W_];
        const float* g = gw + c * 64 + t;
        #pragma unroll
        for (int e = 0; e < E_; e++) part[e] += xv * g[e * 6144];
    }
    #pragma unroll
    for (int off = 16; off; off >>= 1) {
        #pragma unroll
        for (int e = 0; e < E_; e++)
            part[e] += __shfl_xor_sync(0xffffffffu, part[e], off);
    }
    __shared__ float red[2][E_];
    if ((t & 31) == 0) {
        #pragma unroll
        for (int e = 0; e < E_; e++) red[t >> 5][e] = part[e];
    }
    __syncthreads();
    __shared__ float logits[E_];
    if (t < E_) logits[t] = red[0][t] + red[1][t] + g_FS[(ph * 16 + pw) * 8 + t];
    __syncthreads();
    if (t == 0) {
        float mx = logits[0];
        #pragma unroll
        for (int e = 1; e < E_; e++) mx = fmaxf(mx, logits[e]);
        float ex[E_], se = 0.f;
        #pragma unroll
        for (int e = 0; e < E_; e++) { ex[e] = __expf(logits[e] - mx); se += ex[e]; }
        float inv = 1.f / se;
        float* gp = g_gate + ((b * 16 + ph) * 16 + pw) * 8;
        #pragma unroll
        for (int e = 0; e < E_; e++) gp[e] = ex[e] * inv;
    }
}

// ---------------- cp.async helpers
__device__ __forceinline__ void cp16(unsigned dst, const void* src) {
    asm volatile("cp.async.cg.shared.global [%0], [%1], 16;\n" ::
                 "r"(dst), "l"(src));
}
__device__ __forceinline__ void cp4z(unsigned dst, const void* src, int srcsize) {
    asm volatile("cp.async.ca.shared.global [%0], [%1], 4, %2;\n" ::
                 "r"(dst), "l"(src), "r"(srcsize));
}
__device__ __forceinline__ void cp_commit() {
    asm volatile("cp.async.commit_group;\n" ::);
}
__device__ __forceinline__ void cp_wait0() {
    asm volatile("cp.async.wait_group 0;\n" ::);
}

// issue async loads of one k-chunk into a stage buffer
__device__ __forceinline__ void issue_loads(float* stage, const float* __restrict__ x,
                                            int b, int ch, int nb, int x0, int y0, int t) {
    unsigned sb = (unsigned)__cvta_generic_to_shared(stage);
    int k0 = ch * KCHUNK;
    // B tile: 72 rows x 128 floats = 2304 float4
    #pragma unroll
    for (int it = 0; it < 9; it++) {
        int i = t + it * 256;                 // 9*256 = 2304 exactly
        int kl = i >> 5, q = i & 31;
        const float* g = g_w2 + (k0 + kl) * NTOT + nb * 128 + q * 4;
        cp16(sb + (unsigned)((kl * 128 + q * 4) * 4), g);
    }
    // X tile: 8 ic x 10 rows x 18 cols (store pitch 20), zero-filled halo
    unsigned xs = sb + STAGE_B_FLOATS * 4;
    const float* xb = x + (b * C_ + ch * 8) * (H_ * W_);
    #pragma unroll
    for (int it = 0; it < 6; it++) {
        int i = t + it * 256;
        if (i < 1440) {
            int ic = i / 180, rem = i - ic * 180;
            int yy = rem / 18, xx = rem - yy * 18;
            int gy = y0 - 1 + yy, gx = x0 - 1 + xx;
            bool ok = ((unsigned)gy < 128u) && ((unsigned)gx < 128u);
            const float* g = ok ? (xb + ic * (H_ * W_) + gy * W_ + gx) : xb;
            cp4z(xs + (unsigned)((ic * 200 + yy * 20 + xx) * 4), g, ok ? 4 : 0);
        }
    }
}

// ---------------- fused conv + relu + gated combine (double-buffered cp.async)
__global__ void __launch_bounds__(256, 2)
moe_conv(const float* __restrict__ x, const float* __restrict__ eb,
         float* __restrict__ out) {
    extern __shared__ float dynsmem[];
    int bid = blockIdx.x;
    int nb = bid & 3;
    int tx = (bid >> 2) & 7;
    int ty = (bid >> 5) & 15;
    int b  = bid >> 9;
    int x0 = tx * TILE_W, y0 = ty * TILE_H;
    int t = threadIdx.x;
    int n_thr = t & 15, m_thr = t >> 4;
    int r = m_thr >> 1, c0 = (m_thr & 1) * 8;

    float acc[8][8];
    #pragma unroll
    for (int j = 0; j < 8; j++)
        #pragma unroll
        for (int e = 0; e < 8; e++) acc[j][e] = 0.f;

    issue_loads(dynsmem, x, b, 0, nb, x0, y0, t);
    cp_commit();

    for (int ch = 0; ch < NCHUNKS; ++ch) {
        cp_wait0();
        __syncthreads();
        if (ch + 1 < NCHUNKS) {
            issue_loads(dynsmem + ((ch + 1) & 1) * STAGE_FLOATS, x, b, ch + 1, nb, x0, y0, t);
            cp_commit();
        }
        float* stage = dynsmem + (ch & 1) * STAGE_FLOATS;
        float (*Bs)[128]    = (float(*)[128])stage;
        float (*Xs)[10][20] = (float(*)[10][20])(stage + STAGE_B_FLOATS);

        #pragma unroll
        for (int ic = 0; ic < 8; ++ic) {
            #pragma unroll
            for (int dy = 0; dy < 3; ++dy) {
                float row[10];
                const float* rp = &Xs[ic][r + dy][c0];
                float4 t0 = *(const float4*)rp;
                float4 t1 = *(const float4*)(rp + 4);
                row[0] = t0.x; row[1] = t0.y; row[2] = t0.z; row[3] = t0.w;
                row[4] = t1.x; row[5] = t1.y; row[6] = t1.z; row[7] = t1.w;
                row[8] = rp[8]; row[9] = rp[9];
                #pragma unroll
                for (int dx = 0; dx < 3; ++dx) {
                    int kl = ic * 9 + dy * 3 + dx;
                    float4 b0 = *(const float4*)&Bs[kl][n_thr * 8];
                    float4 b1 = *(const float4*)&Bs[kl][n_thr * 8 + 4];
                    #pragma unroll
                    for (int j = 0; j < 8; j++) {
                        float a = row[dx + j];
                        acc[j][0] = fmaf(a, b0.x, acc[j][0]);
                        acc[j][1] = fmaf(a, b0.y, acc[j][1]);
                        acc[j][2] = fmaf(a, b0.z, acc[j][2]);
                        acc[j][3] = fmaf(a, b0.w, acc[j][3]);
                        acc[j][4] = fmaf(a, b1.x, acc[j][4]);
                        acc[j][5] = fmaf(a, b1.y, acc[j][5]);
                        acc[j][6] = fmaf(a, b1.z, acc[j][6]);
                        acc[j][7] = fmaf(a, b1.w, acc[j][7]);
                    }
                }
            }
        }
        __syncthreads();
    }

    // epilogue: bias + relu + gate-weighted sum over experts, write out[b,oc,h,w]
    int oc = nb * 16 + n_thr;
    float bias[8];
    #pragma unroll
    for (int e = 0; e < 8; e++) bias[e] = eb[e * OC_ + oc];

    int h = y0 + r, w0 = x0 + c0;
    int patch = (b * 16 + (h >> 3)) * 16 + (w0 >> 3);
    const float* gp = g_gate + patch * 8;
    float gv[8];
    #pragma unroll
    for (int e = 0; e < 8; e++) gv[e] = gp[e];

    float res[8];
    #pragma unroll
    for (int j = 0; j < 8; j++) {
        float s = 0.f;
        #pragma unroll
        for (int e = 0; e < 8; e++)
            s += gv[e] * fmaxf(acc[j][e] + bias[e], 0.f);
        res[j] = s;
    }
    float* op = out + ((b * OC_ + oc) * H_ + h) * W_ + w0;
    *(float4*)op       = make_float4(res[0], res[1], res[2], res[3]);
    *(float4*)(op + 4) = make_float4(res[4], res[5], res[6], res[7]);
}

extern "C" void kernel_launch(void* const* d_in, const int* in_sizes, int n_in,
                              void* d_out, int out_size) {
    const float* x  = (const float*)d_in[0];
    const float* ew = (const float*)d_in[1];
    const float* eb = (const float*)d_in[2];
    const float* gw = (const float*)d_in[3];
    const float* gb = (const float*)d_in[4];
    float* out = (float*)d_out;

    static bool attr_done = false;
    if (!attr_done) {
        cudaFuncSetAttribute(moe_conv, cudaFuncAttributeMaxDynamicSharedMemorySize,
                             DYN_SMEM_BYTES);
        attr_done = true;
    }

    prep_w<<<(KTOT * NTOT + 255) / 256, 256>>>(ew);
    prep_fs<<<1, 256>>>(gw, gb);
    gate_k<<<B_ * 16 * 16, 64>>>(x, gw);
    moe_conv<<<B_ * 16 * 16 * 4 / 2, 256, DYN_SMEM_BYTES>>>(x, eb, out);
}